// round 13
// baseline (speedup 1.0000x reference)
#include <cuda_runtime.h>
#include <cuda_fp16.h>
#include <mma.h>
#include <cstdint>

using namespace nvcuda;

#define N_NODES  100000
#define N_EDGES  1600000
#define HID      96
#define N_GRAPHS 2048
#define NB       391        // ceil(N_NODES/256)

// ---------------- scratch (device globals; no allocation allowed) ----------
__device__ int    g_deg[N_NODES];
__device__ int    g_rowptr[N_NODES + 1];
__device__ int    g_tick[N_EDGES];
__device__ int    g_col[N_EDGES];
__device__ float  g_dinv[N_NODES];
__device__ __half g_bufA[N_NODES * HID];
__device__ __half g_bufB[N_NODES * HID];
__device__ float  g_pool[N_GRAPHS * HID];
__device__ __half g_wh[3072 + 3 * 9216];   // W1(32x96), W2..W4(96x96) fp16
__device__ int    g_bsum[NB];

// ---------------- helpers ---------------------------------------------------
__device__ __forceinline__ float4 h4_to_f4(uint2 u) {
    __half2 a = *reinterpret_cast<__half2*>(&u.x);
    __half2 b = *reinterpret_cast<__half2*>(&u.y);
    float2 fa = __half22float2(a), fb = __half22float2(b);
    return make_float4(fa.x, fa.y, fb.x, fb.y);
}
__device__ __forceinline__ uint2 f4_to_h4(float4 v) {
    __half2 a = __floats2half2_rn(v.x, v.y);
    __half2 b = __floats2half2_rn(v.z, v.w);
    uint2 u;
    u.x = *reinterpret_cast<uint32_t*>(&a);
    u.y = *reinterpret_cast<uint32_t*>(&b);
    return u;
}
__device__ __forceinline__ void acc_u4(float4& a0, float4& a1, uint4 u) {
    float4 v0 = h4_to_f4(make_uint2(u.x, u.y));
    float4 v1 = h4_to_f4(make_uint2(u.z, u.w));
    a0.x += v0.x; a0.y += v0.y; a0.z += v0.z; a0.w += v0.w;
    a1.x += v1.x; a1.y += v1.y; a1.z += v1.z; a1.w += v1.w;
}

// ---------------- fused prep: zero deg, zero pool, W->fp16 ------------------
__global__ __launch_bounds__(256) void prep_kernel(const float* __restrict__ W1,
                                                   const float* __restrict__ W2,
                                                   const float* __restrict__ W3,
                                                   const float* __restrict__ W4) {
    int i = blockIdx.x * blockDim.x + threadIdx.x;
    if (i < N_NODES) g_deg[i] = 0;
    if (i < N_GRAPHS * HID / 4)
        ((float4*)g_pool)[i] = make_float4(0.f, 0.f, 0.f, 0.f);
    if (i < 3072)                 g_wh[i] = __float2half(W1[i]);
    else if (i < 3072 + 9216)     g_wh[i] = __float2half(W2[i - 3072]);
    else if (i < 3072 + 2 * 9216) g_wh[i] = __float2half(W3[i - 3072 - 9216]);
    else if (i < 3072 + 3 * 9216) g_wh[i] = __float2half(W4[i - 3072 - 2 * 9216]);
}

// ---------------- CSR build (8 edges / thread) ------------------------------
__global__ __launch_bounds__(256) void count_kernel(const int* __restrict__ ei) {
    int t = blockIdx.x * blockDim.x + threadIdx.x;
    if (t < N_EDGES / 8) {
        int4 da = __ldg(&((const int4*)(ei + N_EDGES))[t * 2]);
        int4 db = __ldg(&((const int4*)(ei + N_EDGES))[t * 2 + 1]);
        int4 ta, tb;
        ta.x = atomicAdd(&g_deg[da.x], 1);
        ta.y = atomicAdd(&g_deg[da.y], 1);
        ta.z = atomicAdd(&g_deg[da.z], 1);
        ta.w = atomicAdd(&g_deg[da.w], 1);
        tb.x = atomicAdd(&g_deg[db.x], 1);
        tb.y = atomicAdd(&g_deg[db.y], 1);
        tb.z = atomicAdd(&g_deg[db.z], 1);
        tb.w = atomicAdd(&g_deg[db.w], 1);
        ((int4*)g_tick)[t * 2]     = ta;
        ((int4*)g_tick)[t * 2 + 1] = tb;
    }
}

__global__ __launch_bounds__(256) void scanA_kernel() {
    __shared__ int sh[256];
    int t = threadIdx.x;
    int i = blockIdx.x * 256 + t;
    sh[t] = (i < N_NODES) ? g_deg[i] : 0;
    __syncthreads();
    for (int o = 128; o; o >>= 1) {
        if (t < o) sh[t] += sh[t + o];
        __syncthreads();
    }
    if (t == 0) g_bsum[blockIdx.x] = sh[0];
}

__global__ __launch_bounds__(256) void scanC_kernel() {
    __shared__ int sh[256];
    __shared__ int red[256];
    int t = threadIdx.x;
    int b = blockIdx.x;
    int i = b * 256 + t;
    int d = (i < N_NODES) ? g_deg[i] : 0;

    int part = 0;
    if (t < b)       part += g_bsum[t];
    if (t + 256 < b) part += g_bsum[t + 256];
    red[t] = part;
    __syncthreads();
    for (int o = 128; o; o >>= 1) {
        if (t < o) red[t] += red[t + o];
        __syncthreads();
    }
    int boff = red[0];

    sh[t] = d;
    __syncthreads();
    for (int o = 1; o < 256; o <<= 1) {
        int u = (t >= o) ? sh[t - o] : 0;
        __syncthreads();
        sh[t] += u;
        __syncthreads();
    }
    if (i < N_NODES) {
        g_rowptr[i] = boff + sh[t] - d;
        g_dinv[i]   = rsqrtf((float)(d + 1));
    }
    if (i == 0) g_rowptr[N_NODES] = N_EDGES;
}

__global__ __launch_bounds__(256) void fill_kernel(const int* __restrict__ ei) {
    int t = blockIdx.x * blockDim.x + threadIdx.x;
    if (t < N_EDGES / 8) {
        int4 sa = __ldg(&((const int4*)ei)[t * 2]);
        int4 sb = __ldg(&((const int4*)ei)[t * 2 + 1]);
        int4 da = __ldg(&((const int4*)(ei + N_EDGES))[t * 2]);
        int4 db = __ldg(&((const int4*)(ei + N_EDGES))[t * 2 + 1]);
        int4 ta = __ldg(&((const int4*)g_tick)[t * 2]);
        int4 tb = __ldg(&((const int4*)g_tick)[t * 2 + 1]);
        g_col[g_rowptr[da.x] + ta.x] = sa.x;
        g_col[g_rowptr[da.y] + ta.y] = sa.y;
        g_col[g_rowptr[da.z] + ta.z] = sa.z;
        g_col[g_rowptr[da.w] + ta.w] = sa.w;
        g_col[g_rowptr[db.x] + tb.x] = sb.x;
        g_col[g_rowptr[db.y] + tb.y] = sb.y;
        g_col[g_rowptr[db.z] + tb.z] = sb.z;
        g_col[g_rowptr[db.w] + tb.w] = sb.w;
    }
}

// ---------------- xs0 = half(x * dinv) [N,32] -------------------------------
__global__ __launch_bounds__(256) void scale0_kernel(const float* __restrict__ x,
                                                     __half* __restrict__ out) {
    int idx = blockIdx.x * blockDim.x + threadIdx.x;
    if (idx < N_NODES * 8) {
        int node = idx >> 3;
        float d = g_dinv[node];
        float4 v = ((const float4*)x)[idx];
        v.x *= d; v.y *= d; v.z *= d; v.w *= d;
        ((uint2*)out)[idx] = f4_to_h4(v);
    }
}

// ---------------- fused layer: aggregate + wmma GEMM + epilogue -------------
// Block = 64 nodes, 256 threads (8 warps). Warp MMA tile 16x48 (1x3 frags).
// B fragments load DIRECTLY from global g_wh (L1-resident; no smem staging).
// smem (bytes): sA [0, 64*KP*2) | sC overlay [0, 24576) | sB @24576 | sBatch @24960
template <int KD, bool SCALE_OUT, bool POOL>
__global__ __launch_bounds__(256, 4) void gcn_layer(const __half* __restrict__ Xin,
                                                    __half* __restrict__ Xout,
                                                    const __half* __restrict__ Wh,
                                                    const float* __restrict__ b,
                                                    const int* __restrict__ batch) {
    extern __shared__ __align__(16) char smem[];
    const int KP = KD + 8;                          // sA stride (halves)
    __half* sA = (__half*)smem;
    float*  sC = (float*)smem;
    float*  sB = (float*)(smem + 24576);
    int*    sBatch = (int*)(smem + 24960);

    const int tid = threadIdx.x, wid = tid >> 5, lane = tid & 31;
    const int row0 = blockIdx.x * 64;

    if (tid < 96) sB[tid] = b[tid];
    if (POOL)
        for (int i = tid; i < 64; i += 256)
            sBatch[i] = (row0 + i < N_NODES) ? batch[row0 + i] : -1;

    // ---- phase A: aggregation into sA (16B lanes) ----
    const uint4* x4 = (const uint4*)Xin;
    if (KD == 96) {
        if (lane < 24) {
            const int q = lane % 12;       // uint4 index within row (12 per row)
            const int sub = lane / 12;     // 0..1 : concurrent node
            // prefetch rowptr/dinv/self for all 4 iterations (13 loads in flight)
            int e0a[4], e1a[4];
            float dva[4];
            uint4 selfv[4];
#pragma unroll
            for (int rr = 0; rr < 4; rr++) {
                int node = row0 + wid * 8 + rr * 2 + sub;
                bool ok = node < N_NODES;
                e0a[rr] = ok ? __ldg(&g_rowptr[node])     : 0;
                e1a[rr] = ok ? __ldg(&g_rowptr[node + 1]) : 0;
                dva[rr] = ok ? __ldg(&g_dinv[node])       : 0.f;
                selfv[rr] = ok ? __ldg(&x4[(long)node * 12 + q])
                               : make_uint4(0u, 0u, 0u, 0u);
            }
#pragma unroll
            for (int rr = 0; rr < 4; rr++) {
                int r = wid * 8 + rr * 2 + sub;
                float4 a0 = make_float4(0.f, 0.f, 0.f, 0.f);
                float4 a1 = make_float4(0.f, 0.f, 0.f, 0.f);
                acc_u4(a0, a1, selfv[rr]);
                int e = e0a[rr], e1 = e1a[rr];
                for (; e + 4 <= e1; e += 4) {
                    int s0 = __ldg(&g_col[e + 0]);
                    int s1 = __ldg(&g_col[e + 1]);
                    int s2 = __ldg(&g_col[e + 2]);
                    int s3 = __ldg(&g_col[e + 3]);
                    uint4 u0 = __ldg(&x4[(long)s0 * 12 + q]);
                    uint4 u1 = __ldg(&x4[(long)s1 * 12 + q]);
                    uint4 u2 = __ldg(&x4[(long)s2 * 12 + q]);
                    uint4 u3 = __ldg(&x4[(long)s3 * 12 + q]);
                    acc_u4(a0, a1, u0); acc_u4(a0, a1, u1);
                    acc_u4(a0, a1, u2); acc_u4(a0, a1, u3);
                }
                for (; e < e1; e++) {
                    int s = __ldg(&g_col[e]);
                    acc_u4(a0, a1, __ldg(&x4[(long)s * 12 + q]));
                }
                float d = dva[rr];
                a0.x *= d; a0.y *= d; a0.z *= d; a0.w *= d;
                a1.x *= d; a1.y *= d; a1.z *= d; a1.w *= d;
                uint2 lo = f4_to_h4(a0), hi = f4_to_h4(a1);
                *(uint4*)&sA[r * KP + q * 8] = make_uint4(lo.x, lo.y, hi.x, hi.y);
            }
        }
    } else {  // KD == 32: 4 uint4 per row (32 halves), 8 rows concurrent, all lanes
        const int q = lane & 3;
        const int sub = lane >> 2;     // 0..7
        int r = wid * 8 + sub;
        int node = row0 + r;
        float4 a0 = make_float4(0.f, 0.f, 0.f, 0.f);
        float4 a1 = make_float4(0.f, 0.f, 0.f, 0.f);
        if (node < N_NODES) {
            acc_u4(a0, a1, __ldg(&x4[(long)node * 4 + q]));
            int e0 = g_rowptr[node], e1 = g_rowptr[node + 1];
            int e = e0;
            for (; e + 4 <= e1; e += 4) {
                int s0 = __ldg(&g_col[e + 0]);
                int s1 = __ldg(&g_col[e + 1]);
                int s2 = __ldg(&g_col[e + 2]);
                int s3 = __ldg(&g_col[e + 3]);
                uint4 u0 = __ldg(&x4[(long)s0 * 4 + q]);
                uint4 u1 = __ldg(&x4[(long)s1 * 4 + q]);
                uint4 u2 = __ldg(&x4[(long)s2 * 4 + q]);
                uint4 u3 = __ldg(&x4[(long)s3 * 4 + q]);
                acc_u4(a0, a1, u0); acc_u4(a0, a1, u1);
                acc_u4(a0, a1, u2); acc_u4(a0, a1, u3);
            }
            for (; e < e1; e++) {
                int s = __ldg(&g_col[e]);
                acc_u4(a0, a1, __ldg(&x4[(long)s * 4 + q]));
            }
            float d = g_dinv[node];
            a0.x *= d; a0.y *= d; a0.z *= d; a0.w *= d;
            a1.x *= d; a1.y *= d; a1.z *= d; a1.w *= d;
        }
        uint2 lo = f4_to_h4(a0), hi = f4_to_h4(a1);
        *(uint4*)&sA[r * KP + q * 8] = make_uint4(lo.x, lo.y, hi.x, hi.y);
    }
    __syncthreads();

    // ---- phase B: wmma, warp tile 16x48; B frags from global (L1-hot) ----
    const int wm = (wid >> 1) * 16;
    const int wn = (wid & 1) * 48;

    wmma::fragment<wmma::accumulator, 16, 16, 16, float> acc[3];
#pragma unroll
    for (int j = 0; j < 3; j++) wmma::fill_fragment(acc[j], 0.f);

#pragma unroll
    for (int k0 = 0; k0 < KD; k0 += 16) {
        wmma::fragment<wmma::matrix_a, 16, 16, 16, __half, wmma::row_major> af;
        wmma::fragment<wmma::matrix_b, 16, 16, 16, __half, wmma::row_major> bf[3];
        wmma::load_matrix_sync(af, &sA[wm * KP + k0], KP);
#pragma unroll
        for (int j = 0; j < 3; j++)
            wmma::load_matrix_sync(bf[j], Wh + k0 * 96 + wn + j * 16, 96);
#pragma unroll
        for (int j = 0; j < 3; j++)
            wmma::mma_sync(acc[j], af, bf[j], acc[j]);
    }

    __syncthreads();   // sA done; reuse smem as sC
#pragma unroll
    for (int j = 0; j < 3; j++)
        wmma::store_matrix_sync(&sC[wm * 96 + wn + j * 16], acc[j], 96,
                                wmma::mem_row_major);
    __syncthreads();

    // ---- phase C: epilogue ----
    if (!POOL) {
        for (int i = tid; i < 64 * 24; i += 256) {
            int r = i / 24, c2 = i % 24;
            int row = row0 + r;
            if (row >= N_NODES) continue;
            float d = SCALE_OUT ? g_dinv[row] : 1.f;
            const float* p = &sC[r * 96 + c2 * 4];
            float4 v;
            int c = c2 * 4;
            v.x = fmaxf(p[0] + sB[c + 0], 0.f) * d;
            v.y = fmaxf(p[1] + sB[c + 1], 0.f) * d;
            v.z = fmaxf(p[2] + sB[c + 2], 0.f) * d;
            v.w = fmaxf(p[3] + sB[c + 3], 0.f) * d;
            ((uint2*)&Xout[(long)row * 96])[c2] = f4_to_h4(v);
        }
    } else {
        int rbase = wid * 8;
        if (row0 + rbase < N_NODES) {
            int c = lane * 3;
            float b0 = sB[c], b1 = sB[c + 1], b2 = sB[c + 2];
            int cur = sBatch[rbase];
            float a0 = 0.f, a1 = 0.f, a2 = 0.f;
            for (int rr = 0; rr < 8; rr++) {
                int r = rbase + rr;
                if (row0 + r >= N_NODES) break;
                int bg = sBatch[r];
                if (bg != cur) {
                    atomicAdd(&g_pool[cur * 96 + c + 0], a0);
                    atomicAdd(&g_pool[cur * 96 + c + 1], a1);
                    atomicAdd(&g_pool[cur * 96 + c + 2], a2);
                    a0 = a1 = a2 = 0.f;
                    cur = bg;
                }
                const float* p = &sC[r * 96 + c];
                a0 += fmaxf(p[0] + b0, 0.f);
                a1 += fmaxf(p[1] + b1, 0.f);
                a2 += fmaxf(p[2] + b2, 0.f);
            }
            atomicAdd(&g_pool[cur * 96 + c + 0], a0);
            atomicAdd(&g_pool[cur * 96 + c + 1], a1);
            atomicAdd(&g_pool[cur * 96 + c + 2], a2);
        }
    }
}

// ---------------- final MLP ------------------------------------------------
__global__ __launch_bounds__(128) void mlp_kernel(const float* __restrict__ Wf1,
                                                  const float* __restrict__ bf1,
                                                  const float* __restrict__ Wf2,
                                                  const float* __restrict__ bf2,
                                                  float* __restrict__ out) {
    int g = blockIdx.x * 4 + (threadIdx.x >> 5);
    int j = threadIdx.x & 31;
    if (g >= N_GRAPHS) return;
    float hj = bf1[j];
    const float* gp = &g_pool[g * HID];
#pragma unroll 8
    for (int i = 0; i < 96; i++) hj += gp[i] * Wf1[i * 32 + j];
    hj = fmaxf(hj, 0.f);
    float v = hj * Wf2[j];
#pragma unroll
    for (int off = 16; off; off >>= 1) v += __shfl_down_sync(0xffffffffu, v, off);
    if (j == 0) out[g] = v + bf2[0];
}

// ---------------- launch ---------------------------------------------------
extern "C" void kernel_launch(void* const* d_in, const int* in_sizes, int n_in,
                              void* d_out, int out_size) {
    const float* x     = (const float*)d_in[0];
    const int*   ei    = (const int*)d_in[1];
    const int*   batch = (const int*)d_in[2];
    const float* W1  = (const float*)d_in[3];
    const float* b1  = (const float*)d_in[4];
    const float* W2  = (const float*)d_in[5];
    const float* b2  = (const float*)d_in[6];
    const float* W3  = (const float*)d_in[7];
    const float* b3  = (const float*)d_in[8];
    const float* W4  = (const float*)d_in[9];
    const float* b4  = (const float*)d_in[10];
    const float* Wf1 = (const float*)d_in[11];
    const float* bf1 = (const float*)d_in[12];
    const float* Wf2 = (const float*)d_in[13];
    const float* bf2 = (const float*)d_in[14];
    float* out = (float*)d_out;

    __half *bufA, *bufB, *wh;
    cudaGetSymbolAddress((void**)&bufA, g_bufA);
    cudaGetSymbolAddress((void**)&bufB, g_bufB);
    cudaGetSymbolAddress((void**)&wh, g_wh);

    // smem: sC overlay [0,24576) | sB @24576 (384B) | sBatch @24960 (256B)
    const int SM2 = 25216;
    cudaFuncSetAttribute((const void*)gcn_layer<32, true,  false>, cudaFuncAttributeMaxDynamicSharedMemorySize, SM2);
    cudaFuncSetAttribute((const void*)gcn_layer<96, true,  false>, cudaFuncAttributeMaxDynamicSharedMemorySize, SM2);
    cudaFuncSetAttribute((const void*)gcn_layer<96, false, true >, cudaFuncAttributeMaxDynamicSharedMemorySize, SM2);

    const int TB = 256;
    int nb_e8 = (N_EDGES / 8 + TB - 1) / TB;   // 782

    prep_kernel<<<NB, TB>>>(W1, W2, W3, W4);
    count_kernel<<<nb_e8, TB>>>(ei);
    scanA_kernel<<<NB, TB>>>();
    scanC_kernel<<<NB, TB>>>();
    fill_kernel<<<nb_e8, TB>>>(ei);

    scale0_kernel<<<(N_NODES * 8 + TB - 1) / TB, TB>>>(x, bufA);

    const int L_BLKS = (N_NODES + 63) / 64;   // 1563

    gcn_layer<32, true,  false><<<L_BLKS, 256, SM2>>>(bufA, bufB, wh,                    b1, batch);
    gcn_layer<96, true,  false><<<L_BLKS, 256, SM2>>>(bufB, bufA, wh + 3072,             b2, batch);
    gcn_layer<96, true,  false><<<L_BLKS, 256, SM2>>>(bufA, bufB, wh + 3072 + 9216,      b3, batch);
    gcn_layer<96, false, true ><<<L_BLKS, 256, SM2>>>(bufB, bufA, wh + 3072 + 2 * 9216,  b4, batch);

    mlp_kernel<<<N_GRAPHS / 4, 128>>>(Wf1, bf1, Wf2, bf2, out);
}

// round 14
// speedup vs baseline: 1.1313x; 1.1313x over previous
#include <cuda_runtime.h>
#include <cuda_fp16.h>
#include <mma.h>
#include <cstdint>

using namespace nvcuda;

#define N_NODES  100000
#define N_EDGES  1600000
#define HID      96
#define N_GRAPHS 2048
#define NB       391        // ceil(N_NODES/256)

// ---------------- scratch (device globals; no allocation allowed) ----------
__device__ int    g_deg[N_NODES];
__device__ int    g_rowptr[N_NODES + 1];
__device__ int    g_tick[N_EDGES];
__device__ int    g_col[N_EDGES];
__device__ float  g_dinv[N_NODES];
__device__ __half g_bufA[N_NODES * HID];
__device__ __half g_bufB[N_NODES * HID];
__device__ float  g_pool[N_GRAPHS * HID];
__device__ __half g_wh[3072 + 3 * 9216];   // W1(32x96), W2..W4(96x96) fp16
__device__ int    g_bsum[NB];

// ---------------- helpers ---------------------------------------------------
__device__ __forceinline__ float4 h4_to_f4(uint2 u) {
    __half2 a = *reinterpret_cast<__half2*>(&u.x);
    __half2 b = *reinterpret_cast<__half2*>(&u.y);
    float2 fa = __half22float2(a), fb = __half22float2(b);
    return make_float4(fa.x, fa.y, fb.x, fb.y);
}
__device__ __forceinline__ uint2 f4_to_h4(float4 v) {
    __half2 a = __floats2half2_rn(v.x, v.y);
    __half2 b = __floats2half2_rn(v.z, v.w);
    uint2 u;
    u.x = *reinterpret_cast<uint32_t*>(&a);
    u.y = *reinterpret_cast<uint32_t*>(&b);
    return u;
}
__device__ __forceinline__ void acc_u4(float4& a0, float4& a1, uint4 u) {
    float4 v0 = h4_to_f4(make_uint2(u.x, u.y));
    float4 v1 = h4_to_f4(make_uint2(u.z, u.w));
    a0.x += v0.x; a0.y += v0.y; a0.z += v0.z; a0.w += v0.w;
    a1.x += v1.x; a1.y += v1.y; a1.z += v1.z; a1.w += v1.w;
}

// ---------------- fused prep: zero deg, zero pool, W->fp16 ------------------
__global__ __launch_bounds__(256) void prep_kernel(const float* __restrict__ W1,
                                                   const float* __restrict__ W2,
                                                   const float* __restrict__ W3,
                                                   const float* __restrict__ W4) {
    int i = blockIdx.x * blockDim.x + threadIdx.x;
    if (i < N_NODES) g_deg[i] = 0;
    if (i < N_GRAPHS * HID / 4)
        ((float4*)g_pool)[i] = make_float4(0.f, 0.f, 0.f, 0.f);
    if (i < 3072)                 g_wh[i] = __float2half(W1[i]);
    else if (i < 3072 + 9216)     g_wh[i] = __float2half(W2[i - 3072]);
    else if (i < 3072 + 2 * 9216) g_wh[i] = __float2half(W3[i - 3072 - 9216]);
    else if (i < 3072 + 3 * 9216) g_wh[i] = __float2half(W4[i - 3072 - 2 * 9216]);
}

// ---------------- CSR build (8 edges / thread) ------------------------------
__global__ __launch_bounds__(256) void count_kernel(const int* __restrict__ ei) {
    int t = blockIdx.x * blockDim.x + threadIdx.x;
    if (t < N_EDGES / 8) {
        int4 da = __ldg(&((const int4*)(ei + N_EDGES))[t * 2]);
        int4 db = __ldg(&((const int4*)(ei + N_EDGES))[t * 2 + 1]);
        int4 ta, tb;
        ta.x = atomicAdd(&g_deg[da.x], 1);
        ta.y = atomicAdd(&g_deg[da.y], 1);
        ta.z = atomicAdd(&g_deg[da.z], 1);
        ta.w = atomicAdd(&g_deg[da.w], 1);
        tb.x = atomicAdd(&g_deg[db.x], 1);
        tb.y = atomicAdd(&g_deg[db.y], 1);
        tb.z = atomicAdd(&g_deg[db.z], 1);
        tb.w = atomicAdd(&g_deg[db.w], 1);
        ((int4*)g_tick)[t * 2]     = ta;
        ((int4*)g_tick)[t * 2 + 1] = tb;
    }
}

__global__ __launch_bounds__(256) void scanA_kernel() {
    __shared__ int sh[256];
    int t = threadIdx.x;
    int i = blockIdx.x * 256 + t;
    sh[t] = (i < N_NODES) ? g_deg[i] : 0;
    __syncthreads();
    for (int o = 128; o; o >>= 1) {
        if (t < o) sh[t] += sh[t + o];
        __syncthreads();
    }
    if (t == 0) g_bsum[blockIdx.x] = sh[0];
}

__global__ __launch_bounds__(256) void scanC_kernel() {
    __shared__ int sh[256];
    __shared__ int red[256];
    int t = threadIdx.x;
    int b = blockIdx.x;
    int i = b * 256 + t;
    int d = (i < N_NODES) ? g_deg[i] : 0;

    int part = 0;
    if (t < b)       part += g_bsum[t];
    if (t + 256 < b) part += g_bsum[t + 256];
    red[t] = part;
    __syncthreads();
    for (int o = 128; o; o >>= 1) {
        if (t < o) red[t] += red[t + o];
        __syncthreads();
    }
    int boff = red[0];

    sh[t] = d;
    __syncthreads();
    for (int o = 1; o < 256; o <<= 1) {
        int u = (t >= o) ? sh[t - o] : 0;
        __syncthreads();
        sh[t] += u;
        __syncthreads();
    }
    if (i < N_NODES) {
        g_rowptr[i] = boff + sh[t] - d;
        g_dinv[i]   = rsqrtf((float)(d + 1));
    }
    if (i == 0) g_rowptr[N_NODES] = N_EDGES;
}

__global__ __launch_bounds__(256) void fill_kernel(const int* __restrict__ ei) {
    int t = blockIdx.x * blockDim.x + threadIdx.x;
    if (t < N_EDGES / 8) {
        int4 sa = __ldg(&((const int4*)ei)[t * 2]);
        int4 sb = __ldg(&((const int4*)ei)[t * 2 + 1]);
        int4 da = __ldg(&((const int4*)(ei + N_EDGES))[t * 2]);
        int4 db = __ldg(&((const int4*)(ei + N_EDGES))[t * 2 + 1]);
        int4 ta = __ldg(&((const int4*)g_tick)[t * 2]);
        int4 tb = __ldg(&((const int4*)g_tick)[t * 2 + 1]);
        g_col[g_rowptr[da.x] + ta.x] = sa.x;
        g_col[g_rowptr[da.y] + ta.y] = sa.y;
        g_col[g_rowptr[da.z] + ta.z] = sa.z;
        g_col[g_rowptr[da.w] + ta.w] = sa.w;
        g_col[g_rowptr[db.x] + tb.x] = sb.x;
        g_col[g_rowptr[db.y] + tb.y] = sb.y;
        g_col[g_rowptr[db.z] + tb.z] = sb.z;
        g_col[g_rowptr[db.w] + tb.w] = sb.w;
    }
}

// ---------------- xs0 = half(x * dinv) [N,32] -------------------------------
__global__ __launch_bounds__(256) void scale0_kernel(const float* __restrict__ x,
                                                     __half* __restrict__ out) {
    int idx = blockIdx.x * blockDim.x + threadIdx.x;
    if (idx < N_NODES * 8) {
        int node = idx >> 3;
        float d = g_dinv[node];
        float4 v = ((const float4*)x)[idx];
        v.x *= d; v.y *= d; v.z *= d; v.w *= d;
        ((uint2*)out)[idx] = f4_to_h4(v);
    }
}

// ---------------- fused layer: aggregate + wmma GEMM + epilogue -------------
// Block = 64 nodes, 256 threads (8 warps). Warp MMA tile 16x48 (1x3 frags).
// sW staged in smem, padded stride 104 halves (conflict-free B frag loads).
// smem (bytes): sA [0,64*KP*2) | sW [64*KP*2, +KD*104*2) | sC overlay [0,24576)
//               sB @33280 | sBatch @33664
template <int KD, bool SCALE_OUT, bool POOL>
__global__ __launch_bounds__(256, 4) void gcn_layer(const __half* __restrict__ Xin,
                                                    __half* __restrict__ Xout,
                                                    const __half* __restrict__ Wh,
                                                    const float* __restrict__ b,
                                                    const int* __restrict__ batch) {
    extern __shared__ __align__(16) char smem[];
    const int KP = KD + 8;                          // sA stride (halves)
    const int WP = 104;                             // sW stride (halves)
    __half* sA = (__half*)smem;
    __half* sW = (__half*)(smem + 64 * KP * 2);
    float*  sC = (float*)smem;
    float*  sB = (float*)(smem + 33280);
    int*    sBatch = (int*)(smem + 33664);

    const int tid = threadIdx.x, wid = tid >> 5, lane = tid & 31;
    const int row0 = blockIdx.x * 64;

    for (int i = tid; i < KD * 12; i += 256) {
        int r = i / 12, c = i % 12;
        ((uint4*)(sW + r * WP))[c] = ((const uint4*)(Wh + r * 96))[c];
    }
    if (tid < 96) sB[tid] = b[tid];
    if (POOL)
        for (int i = tid; i < 64; i += 256)
            sBatch[i] = (row0 + i < N_NODES) ? batch[row0 + i] : -1;

    // ---- phase A: aggregation into sA (16B lanes) ----
    const uint4* x4 = (const uint4*)Xin;
    if (KD == 96) {
        if (lane < 24) {
            const int q = lane % 12;       // uint4 index within row (12 per row)
            const int sub = lane / 12;     // 0..1 : concurrent node
            // prefetch rowptr/dinv/self for all 4 iterations
            int e0a[4], e1a[4];
            float dva[4];
            uint4 selfv[4];
#pragma unroll
            for (int rr = 0; rr < 4; rr++) {
                int node = row0 + wid * 8 + rr * 2 + sub;
                bool ok = node < N_NODES;
                e0a[rr] = ok ? __ldg(&g_rowptr[node])     : 0;
                e1a[rr] = ok ? __ldg(&g_rowptr[node + 1]) : 0;
                dva[rr] = ok ? __ldg(&g_dinv[node])       : 0.f;
                selfv[rr] = ok ? __ldg(&x4[(long)node * 12 + q])
                               : make_uint4(0u, 0u, 0u, 0u);
            }
#pragma unroll
            for (int rr = 0; rr < 4; rr++) {
                int r = wid * 8 + rr * 2 + sub;
                float4 a0 = make_float4(0.f, 0.f, 0.f, 0.f);
                float4 a1 = make_float4(0.f, 0.f, 0.f, 0.f);
                acc_u4(a0, a1, selfv[rr]);
                int e = e0a[rr], e1 = e1a[rr];
                for (; e + 4 <= e1; e += 4) {
                    int s0 = __ldg(&g_col[e + 0]);
                    int s1 = __ldg(&g_col[e + 1]);
                    int s2 = __ldg(&g_col[e + 2]);
                    int s3 = __ldg(&g_col[e + 3]);
                    uint4 u0 = __ldg(&x4[(long)s0 * 12 + q]);
                    uint4 u1 = __ldg(&x4[(long)s1 * 12 + q]);
                    uint4 u2 = __ldg(&x4[(long)s2 * 12 + q]);
                    uint4 u3 = __ldg(&x4[(long)s3 * 12 + q]);
                    acc_u4(a0, a1, u0); acc_u4(a0, a1, u1);
                    acc_u4(a0, a1, u2); acc_u4(a0, a1, u3);
                }
                for (; e < e1; e++) {
                    int s = __ldg(&g_col[e]);
                    acc_u4(a0, a1, __ldg(&x4[(long)s * 12 + q]));
                }
                float d = dva[rr];
                a0.x *= d; a0.y *= d; a0.z *= d; a0.w *= d;
                a1.x *= d; a1.y *= d; a1.z *= d; a1.w *= d;
                uint2 lo = f4_to_h4(a0), hi = f4_to_h4(a1);
                *(uint4*)&sA[r * KP + q * 8] = make_uint4(lo.x, lo.y, hi.x, hi.y);
            }
        }
    } else {  // KD == 32: 4 uint4 per row (32 halves), 8 rows concurrent, all lanes
        const int q = lane & 3;
        const int sub = lane >> 2;     // 0..7
        int r = wid * 8 + sub;
        int node = row0 + r;
        float4 a0 = make_float4(0.f, 0.f, 0.f, 0.f);
        float4 a1 = make_float4(0.f, 0.f, 0.f, 0.f);
        if (node < N_NODES) {
            acc_u4(a0, a1, __ldg(&x4[(long)node * 4 + q]));
            int e0 = g_rowptr[node], e1 = g_rowptr[node + 1];
            int e = e0;
            for (; e + 4 <= e1; e += 4) {
                int s0 = __ldg(&g_col[e + 0]);
                int s1 = __ldg(&g_col[e + 1]);
                int s2 = __ldg(&g_col[e + 2]);
                int s3 = __ldg(&g_col[e + 3]);
                uint4 u0 = __ldg(&x4[(long)s0 * 4 + q]);
                uint4 u1 = __ldg(&x4[(long)s1 * 4 + q]);
                uint4 u2 = __ldg(&x4[(long)s2 * 4 + q]);
                uint4 u3 = __ldg(&x4[(long)s3 * 4 + q]);
                acc_u4(a0, a1, u0); acc_u4(a0, a1, u1);
                acc_u4(a0, a1, u2); acc_u4(a0, a1, u3);
            }
            for (; e < e1; e++) {
                int s = __ldg(&g_col[e]);
                acc_u4(a0, a1, __ldg(&x4[(long)s * 4 + q]));
            }
            float d = g_dinv[node];
            a0.x *= d; a0.y *= d; a0.z *= d; a0.w *= d;
            a1.x *= d; a1.y *= d; a1.z *= d; a1.w *= d;
        }
        uint2 lo = f4_to_h4(a0), hi = f4_to_h4(a1);
        *(uint4*)&sA[r * KP + q * 8] = make_uint4(lo.x, lo.y, hi.x, hi.y);
    }
    __syncthreads();

    // ---- phase B: wmma, warp tile 16x48 ----
    const int wm = (wid >> 1) * 16;
    const int wn = (wid & 1) * 48;

    wmma::fragment<wmma::accumulator, 16, 16, 16, float> acc[3];
#pragma unroll
    for (int j = 0; j < 3; j++) wmma::fill_fragment(acc[j], 0.f);

#pragma unroll
    for (int k0 = 0; k0 < KD; k0 += 16) {
        wmma::fragment<wmma::matrix_a, 16, 16, 16, __half, wmma::row_major> af;
        wmma::fragment<wmma::matrix_b, 16, 16, 16, __half, wmma::row_major> bf[3];
        wmma::load_matrix_sync(af, &sA[wm * KP + k0], KP);
#pragma unroll
        for (int j = 0; j < 3; j++)
            wmma::load_matrix_sync(bf[j], &sW[k0 * WP + wn + j * 16], WP);
#pragma unroll
        for (int j = 0; j < 3; j++)
            wmma::mma_sync(acc[j], af, bf[j], acc[j]);
    }

    __syncthreads();
#pragma unroll
    for (int j = 0; j < 3; j++)
        wmma::store_matrix_sync(&sC[wm * 96 + wn + j * 16], acc[j], 96,
                                wmma::mem_row_major);
    __syncthreads();

    // ---- phase C: epilogue ----
    if (!POOL) {
        for (int i = tid; i < 64 * 24; i += 256) {
            int r = i / 24, c2 = i % 24;
            int row = row0 + r;
            if (row >= N_NODES) continue;
            float d = SCALE_OUT ? g_dinv[row] : 1.f;
            const float* p = &sC[r * 96 + c2 * 4];
            float4 v;
            int c = c2 * 4;
            v.x = fmaxf(p[0] + sB[c + 0], 0.f) * d;
            v.y = fmaxf(p[1] + sB[c + 1], 0.f) * d;
            v.z = fmaxf(p[2] + sB[c + 2], 0.f) * d;
            v.w = fmaxf(p[3] + sB[c + 3], 0.f) * d;
            ((uint2*)&Xout[(long)row * 96])[c2] = f4_to_h4(v);
        }
    } else {
        int rbase = wid * 8;
        if (row0 + rbase < N_NODES) {
            int c = lane * 3;
            float b0 = sB[c], b1 = sB[c + 1], b2 = sB[c + 2];
            int cur = sBatch[rbase];
            float a0 = 0.f, a1 = 0.f, a2 = 0.f;
            for (int rr = 0; rr < 8; rr++) {
                int r = rbase + rr;
                if (row0 + r >= N_NODES) break;
                int bg = sBatch[r];
                if (bg != cur) {
                    atomicAdd(&g_pool[cur * 96 + c + 0], a0);
                    atomicAdd(&g_pool[cur * 96 + c + 1], a1);
                    atomicAdd(&g_pool[cur * 96 + c + 2], a2);
                    a0 = a1 = a2 = 0.f;
                    cur = bg;
                }
                const float* p = &sC[r * 96 + c];
                a0 += fmaxf(p[0] + b0, 0.f);
                a1 += fmaxf(p[1] + b1, 0.f);
                a2 += fmaxf(p[2] + b2, 0.f);
            }
            atomicAdd(&g_pool[cur * 96 + c + 0], a0);
            atomicAdd(&g_pool[cur * 96 + c + 1], a1);
            atomicAdd(&g_pool[cur * 96 + c + 2], a2);
        }
    }
}

// ---------------- final MLP ------------------------------------------------
__global__ __launch_bounds__(128) void mlp_kernel(const float* __restrict__ Wf1,
                                                  const float* __restrict__ bf1,
                                                  const float* __restrict__ Wf2,
                                                  const float* __restrict__ bf2,
                                                  float* __restrict__ out) {
    int g = blockIdx.x * 4 + (threadIdx.x >> 5);
    int j = threadIdx.x & 31;
    if (g >= N_GRAPHS) return;
    float hj = bf1[j];
    const float* gp = &g_pool[g * HID];
#pragma unroll 8
    for (int i = 0; i < 96; i++) hj += gp[i] * Wf1[i * 32 + j];
    hj = fmaxf(hj, 0.f);
    float v = hj * Wf2[j];
#pragma unroll
    for (int off = 16; off; off >>= 1) v += __shfl_down_sync(0xffffffffu, v, off);
    if (j == 0) out[g] = v + bf2[0];
}

// ---------------- launch ---------------------------------------------------
extern "C" void kernel_launch(void* const* d_in, const int* in_sizes, int n_in,
                              void* d_out, int out_size) {
    const float* x     = (const float*)d_in[0];
    const int*   ei    = (const int*)d_in[1];
    const int*   batch = (const int*)d_in[2];
    const float* W1  = (const float*)d_in[3];
    const float* b1  = (const float*)d_in[4];
    const float* W2  = (const float*)d_in[5];
    const float* b2  = (const float*)d_in[6];
    const float* W3  = (const float*)d_in[7];
    const float* b3  = (const float*)d_in[8];
    const float* W4  = (const float*)d_in[9];
    const float* b4  = (const float*)d_in[10];
    const float* Wf1 = (const float*)d_in[11];
    const float* bf1 = (const float*)d_in[12];
    const float* Wf2 = (const float*)d_in[13];
    const float* bf2 = (const float*)d_in[14];
    float* out = (float*)d_out;

    __half *bufA, *bufB, *wh;
    cudaGetSymbolAddress((void**)&bufA, g_bufA);
    cudaGetSymbolAddress((void**)&bufB, g_bufB);
    cudaGetSymbolAddress((void**)&wh, g_wh);

    const int SM2 = 33920;
    cudaFuncSetAttribute((const void*)gcn_layer<32, true,  false>, cudaFuncAttributeMaxDynamicSharedMemorySize, SM2);
    cudaFuncSetAttribute((const void*)gcn_layer<96, true,  false>, cudaFuncAttributeMaxDynamicSharedMemorySize, SM2);
    cudaFuncSetAttribute((const void*)gcn_layer<96, false, true >, cudaFuncAttributeMaxDynamicSharedMemorySize, SM2);

    const int TB = 256;
    int nb_e8 = (N_EDGES / 8 + TB - 1) / TB;   // 782

    prep_kernel<<<NB, TB>>>(W1, W2, W3, W4);
    count_kernel<<<nb_e8, TB>>>(ei);
    scanA_kernel<<<NB, TB>>>();
    scanC_kernel<<<NB, TB>>>();
    fill_kernel<<<nb_e8, TB>>>(ei);

    scale0_kernel<<<(N_NODES * 8 + TB - 1) / TB, TB>>>(x, bufA);

    const int L_BLKS = (N_NODES + 63) / 64;   // 1563

    gcn_layer<32, true,  false><<<L_BLKS, 256, SM2>>>(bufA, bufB, wh,                    b1, batch);
    gcn_layer<96, true,  false><<<L_BLKS, 256, SM2>>>(bufB, bufA, wh + 3072,             b2, batch);
    gcn_layer<96, true,  false><<<L_BLKS, 256, SM2>>>(bufA, bufB, wh + 3072 + 9216,      b3, batch);
    gcn_layer<96, false, true ><<<L_BLKS, 256, SM2>>>(bufB, bufA, wh + 3072 + 2 * 9216,  b4, batch);

    mlp_kernel<<<N_GRAPHS / 4, 128>>>(Wf1, bf1, Wf2, bf2, out);
}